// round 2
// baseline (speedup 1.0000x reference)
#include <cuda_runtime.h>

// PLIF spiking neuron forward:
//   x: [B=32, T=8, C=128, H=32, W=32] f32, tau: [C=128] f32
//   tau_s = sigmoid(tau[c])
//   scan over t: mem = mem*tau_s + x_t; spike = (mem - 1 > 0); mem = (1-spike)*mem
//   out: spikes, same shape as x.
//
// Memory-bound streaming kernel: 256 MiB total traffic. One thread owns one
// (b,c,h,w0..w0+3) site via float4, loads all T=8 timesteps up front (MLP=8),
// runs the scan in registers, stores 8 float4 results.

constexpr int B = 32, T = 8, C = 128, H = 32, W = 32;
constexpr int HW   = H * W;          // 1024
constexpr int CHW  = C * HW;         // 131072 (= 2^17)
constexpr int TCHW = T * CHW;        // 1048576
constexpr int N4   = (B * CHW) / 4;  // 1048576 float4-threads

__global__ __launch_bounds__(256) void plif_kernel(
    const float4* __restrict__ x4,
    const float*  __restrict__ tau,
    float4*       __restrict__ out4)
{
    int idx = blockIdx.x * blockDim.x + threadIdx.x;
    if (idx >= N4) return;

    int e   = idx << 2;              // element index within [B, C, H, W] flat
    int b   = e >> 17;               // / CHW
    int rem = e & (CHW - 1);         // within one (C,H,W) slab
    int c   = rem >> 10;             // / HW

    // per-channel leak (broadcast within warp; precise sigmoid)
    float ts = 1.0f / (1.0f + expf(-tau[c]));

    // float4 base index of timestep 0 for this site
    int base = (b * TCHW + rem) >> 2;
    constexpr int tstride = CHW >> 2;  // float4 stride between timesteps

    // Prefetch all T timesteps (independent loads -> MLP=8)
    float4 v[T];
#pragma unroll
    for (int t = 0; t < T; t++)
        v[t] = x4[base + t * tstride];

    float4 mem = make_float4(0.f, 0.f, 0.f, 0.f);
#pragma unroll
    for (int t = 0; t < T; t++) {
        float4 s;
        mem.x = mem.x * ts + v[t].x;
        mem.y = mem.y * ts + v[t].y;
        mem.z = mem.z * ts + v[t].z;
        mem.w = mem.w * ts + v[t].w;
        s.x = (mem.x > 1.0f) ? 1.0f : 0.0f;
        s.y = (mem.y > 1.0f) ? 1.0f : 0.0f;
        s.z = (mem.z > 1.0f) ? 1.0f : 0.0f;
        s.w = (mem.w > 1.0f) ? 1.0f : 0.0f;
        // hard reset: mem = (1-spike)*mem
        if (s.x != 0.0f) mem.x = 0.0f;
        if (s.y != 0.0f) mem.y = 0.0f;
        if (s.z != 0.0f) mem.z = 0.0f;
        if (s.w != 0.0f) mem.w = 0.0f;
        out4[base + t * tstride] = s;
    }
}

extern "C" void kernel_launch(void* const* d_in, const int* in_sizes, int n_in,
                              void* d_out, int out_size)
{
    const float4* x4  = (const float4*)d_in[0];
    const float*  tau = (const float*)d_in[1];
    float4*       o4  = (float4*)d_out;

    int threads = 256;
    int blocks  = (N4 + threads - 1) / threads;  // 4096
    plif_kernel<<<blocks, threads>>>(x4, tau, o4);
}

// round 3
// speedup vs baseline: 1.0092x; 1.0092x over previous
#include <cuda_runtime.h>

// PLIF spiking neuron forward:
//   x: [B=32, T=8, C=128, H=32, W=32] f32, tau: [C=128] f32
//   tau_s = sigmoid(tau[c])
//   scan over t: mem = mem*tau_s + x_t; spike = (mem - 1 > 0); mem = (1-spike)*mem
//   out: spikes, same shape as x.
//
// Pure 256 MiB streaming workload (zero reuse). One thread owns one
// (b,c,w-quad) site via float4:
//   - 8 front-batched __ldcs float4 loads (MLP=8, evict-first: don't pollute L2)
//   - scan in registers, spike overwrites v[t] in place
//   - 8 back-to-back __stcs float4 stores (streaming writes)

constexpr int B = 32, T = 8, C = 128, H = 32, W = 32;
constexpr int HW   = H * W;          // 1024
constexpr int CHW  = C * HW;         // 131072 (= 2^17)
constexpr int TCHW = T * CHW;        // 1048576
constexpr int N4   = (B * CHW) / 4;  // 1048576 float4-threads

__global__ __launch_bounds__(256) void plif_kernel(
    const float4* __restrict__ x4,
    const float*  __restrict__ tau,
    float4*       __restrict__ out4)
{
    int idx = blockIdx.x * blockDim.x + threadIdx.x;
    if (idx >= N4) return;

    int e   = idx << 2;              // element index within [B, C, H, W] flat
    int b   = e >> 17;               // / CHW
    int rem = e & (CHW - 1);         // within one (C,H,W) slab
    int c   = rem >> 10;             // / HW

    // per-channel leak (broadcast within warp; precise sigmoid)
    float ts = 1.0f / (1.0f + expf(-tau[c]));

    // float4 base index of timestep 0 for this site
    int base = (b * TCHW + rem) >> 2;
    constexpr int tstride = CHW >> 2;  // float4 stride between timesteps

    // Front-batched streaming loads: 8 independent LDG.128.CS in flight
    float4 v[T];
#pragma unroll
    for (int t = 0; t < T; t++)
        v[t] = __ldcs(&x4[base + t * tstride]);

    // Register scan; spike result overwrites the consumed input slot
    float4 mem = make_float4(0.f, 0.f, 0.f, 0.f);
#pragma unroll
    for (int t = 0; t < T; t++) {
        mem.x = mem.x * ts + v[t].x;
        mem.y = mem.y * ts + v[t].y;
        mem.z = mem.z * ts + v[t].z;
        mem.w = mem.w * ts + v[t].w;
        float sx = (mem.x > 1.0f) ? 1.0f : 0.0f;
        float sy = (mem.y > 1.0f) ? 1.0f : 0.0f;
        float sz = (mem.z > 1.0f) ? 1.0f : 0.0f;
        float sw = (mem.w > 1.0f) ? 1.0f : 0.0f;
        // hard reset: mem = (1-spike)*mem
        if (sx != 0.0f) mem.x = 0.0f;
        if (sy != 0.0f) mem.y = 0.0f;
        if (sz != 0.0f) mem.z = 0.0f;
        if (sw != 0.0f) mem.w = 0.0f;
        v[t].x = sx; v[t].y = sy; v[t].z = sz; v[t].w = sw;
    }

    // Back-to-back streaming stores
#pragma unroll
    for (int t = 0; t < T; t++)
        __stcs(&out4[base + t * tstride], v[t]);
}

extern "C" void kernel_launch(void* const* d_in, const int* in_sizes, int n_in,
                              void* d_out, int out_size)
{
    const float4* x4  = (const float4*)d_in[0];
    const float*  tau = (const float*)d_in[1];
    float4*       o4  = (float4*)d_out;

    int threads = 256;
    int blocks  = (N4 + threads - 1) / threads;  // 4096
    plif_kernel<<<blocks, threads>>>(x4, tau, o4);
}